// round 16
// baseline (speedup 1.0000x reference)
#include <cuda_runtime.h>
#include <cuda_fp16.h>
#include <cstdint>

#define Bn 16
#define Fn 257
#define FPAD 272
#define Tn 8000
#define NBn 64
#define TTILE 128
#define KSTEPS 17

// ---- staged scan v5 config (2 blocks/SM, no staging) ----
#define NCH 8
#define CHUNK 1000
#define WARM 128
#define LOCAL (WARM + CHUNK)          // 1128
#define STILE 32
#define NTILE 36                      // 36*32 = 1152 >= 1128
#define WTILES (WARM / STILE)         // 4 dead tiles for chunk 0
#define ROWST 36                      // floats: 9 quad-banks, gcd(9,32)=1 -> LDS.128 conflict-free
#define WBUF (32 * ROWST)             // 1152 floats
#define SCAN_SMEM (8 * 2 * WBUF * 4)  // 73728 B -> 2 blocks/SM
#define SCAN_GRID (Bn * 9)            // 144

// ---- band GEMM config ----
#define AST 136
#define BST 280
#define OST 132
#define A_BYTES (FPAD * AST * 2)
#define B_BYTES (NBn * BST * 2)
#define SMEM_TOTAL (A_BYTES + B_BYTES)
#define KSPLIT 9

// 65.8 MB fp16 scratch: g_vnr[b][f][t] = vnr/10 (t-contiguous)
__device__ __align__(128) __half g_vnr[(size_t)Bn * Fn * Tn];
__device__ __align__(128) __half g_fbh[NBn * BST];

struct __align__(16) H8 { __half2 a, b, c, d; };

__device__ __forceinline__ uint32_t smem_u32(const void* p) {
    uint32_t a;
    asm("{ .reg .u64 t; cvta.to.shared.u64 t, %1; cvt.u32.u64 %0, t; }" : "=r"(a) : "l"(p));
    return a;
}
__device__ __forceinline__ void cpasync16(uint32_t dst, const void* src, int sz) {
    asm volatile("cp.async.ca.shared.global [%0], [%1], 16, %2;" :: "r"(dst), "l"(src), "r"(sz));
}
__device__ __forceinline__ void cp_commit() { asm volatile("cp.async.commit_group;" ::: "memory"); }
__device__ __forceinline__ void cp_wait0()  { asm volatile("cp.async.wait_group 0;" ::: "memory"); }
__device__ __forceinline__ void cp_wait1()  { asm volatile("cp.async.wait_group 1;" ::: "memory"); }

__device__ __forceinline__ void ldsm_x4_t(uint32_t a[4], uint32_t addr) {
    asm volatile("ldmatrix.sync.aligned.m8n8.x4.trans.shared.b16 {%0,%1,%2,%3}, [%4];"
        : "=r"(a[0]), "=r"(a[1]), "=r"(a[2]), "=r"(a[3]) : "r"(addr));
}
__device__ __forceinline__ void ldsm_x4(uint32_t a[4], uint32_t addr) {
    asm volatile("ldmatrix.sync.aligned.m8n8.x4.shared.b16 {%0,%1,%2,%3}, [%4];"
        : "=r"(a[0]), "=r"(a[1]), "=r"(a[2]), "=r"(a[3]) : "r"(addr));
}
__device__ __forceinline__ void mma16816(float d[4], const uint32_t a[4], uint32_t b0, uint32_t b1) {
    asm volatile("mma.sync.aligned.m16n8k16.row.col.f32.f16.f16.f32 "
        "{%0,%1,%2,%3}, {%4,%5,%6,%7}, {%8,%9}, {%0,%1,%2,%3};"
        : "+f"(d[0]), "+f"(d[1]), "+f"(d[2]), "+f"(d[3])
        : "r"(a[0]), "r"(a[1]), "r"(a[2]), "r"(a[3]), "r"(b0), "r"(b1));
}
__device__ __forceinline__ float tanh_fast(float x) {
    float y; asm("tanh.approx.f32 %0, %1;" : "=f"(y) : "f"(x)); return y;
}

// 12-cyc chain step: cr/cf computed as fma(nf, 1-a, a*x) with a*x precomputed
__device__ __forceinline__ float nf_step2(float rx, float fx, float nf,
                                          float cr1, float cf1, float fl) {
    float cr = fmaf(nf, cr1, rx);
    float cf = fmaf(nf, cf1, fx);
    return fmaxf(fmaxf(cr, cf), fl);
}

// ============================================================
// K1: staged scan v5 -> g_vnr fp16 (vnr/10)
// Block = (b, fg): 32 chains x 8 chunk-warps. 73.7KB smem -> 2 blocks/SM.
// Coalesced cp.async.16 tiles (depth-2, wait_group 1), conflict-free
// LDS.128, direct per-lane H8 stores (r11-proven). No block syncs.
// Blocks >= SCAN_GRID: fused fb conversion.
// ============================================================
extern __shared__ float s_scan[];

__global__ __launch_bounds__(256, 2) void scan_kernel(
    const float* __restrict__ mag,
    const float* __restrict__ fbw,
    const float* __restrict__ p_ns,
    const float* __restrict__ p_rr,
    const float* __restrict__ p_rf)
{
    if (blockIdx.x >= SCAN_GRID) {
        int base = (blockIdx.x - SCAN_GRID) * 256 + threadIdx.x;
        for (int i = base; i < NBn * BST; i += 256 * 8) {
            int n = i / BST;
            int f = i - n * BST;
            g_fbh[i] = (f < Fn) ? __float2half_rn(__ldg(fbw + n * Fn + f)) : __float2half_rn(0.0f);
        }
        return;
    }

    const int bb = blockIdx.x / 9;
    const int fg = blockIdx.x % 9;
    const int c  = threadIdx.x >> 5;   // chunk (warp)
    const int l  = threadIdx.x & 31;   // chain lane

    const uint32_t sbase = smem_u32(s_scan);

    const float rise = 1.0f / (1.0f + expf(-__ldg(p_rr)));
    const float fall = 1.0f / (1.0f + expf(-__ldg(p_rf)));
    const float cr1 = 1.0f - rise;
    const float cf1 = 1.0f - fall;
    const float ns10 = 10.0f * fabsf(__ldg(p_ns));

    const int fmine = fg * 32 + l;
    const bool fvalid = (fmine < Fn);
    const size_t myrow = ((size_t)bb * Fn + (fvalid ? fmine : 0)) * Tn;

    // init min over first 20 frames: 5 x LDG.128
    const float4* ir = reinterpret_cast<const float4*>(mag + myrow);
    float4 a0 = __ldg(ir), a1 = __ldg(ir + 1), a2 = __ldg(ir + 2),
           a3 = __ldg(ir + 3), a4 = __ldg(ir + 4);
    float mn = fminf(fminf(fminf(a0.x, a0.y), fminf(a0.z, a0.w)),
               fminf(fminf(fminf(a1.x, a1.y), fminf(a1.z, a1.w)),
               fminf(fminf(fminf(a2.x, a2.y), fminf(a2.z, a2.w)),
               fminf(fminf(fminf(a3.x, a3.y), fminf(a3.z, a3.w)),
                     fminf(fminf(a4.x, a4.y), fminf(a4.z, a4.w))))));
    mn = fmaxf(mn, 1e-5f);
    const float fl_ = 0.5f * mn;
    float nf = mn;

    const int t0base = c * CHUNK - WARM;
    const float* magb = mag + (size_t)bb * Fn * Tn;
    __half* myout = g_vnr + myrow;     // valid only if fvalid

    // per warp-tile: 32 rows x 128 B -> 8 cp.async.16 per lane
    #define ISSUE(k, sel) { \
        const int t0g = t0base + (k) * STILE; \
        const uint32_t dbase = sbase + (uint32_t)((c * 2 + (sel)) * WBUF * 4); \
        _Pragma("unroll") \
        for (int it = 0; it < 8; ++it) { \
            int o = l + 32 * it; \
            int m = o >> 3; \
            int seg = o & 7; \
            int tt = t0g + seg * 4; \
            int fm = fg * 32 + m; \
            int sz = (tt >= 0 && tt + 4 <= Tn && fm < Fn) ? 16 : 0; \
            int ttc = (tt < 0) ? 0 : ((tt + 4 > Tn) ? (Tn - 4) : tt); \
            int fmc = (fm < Fn) ? fm : 0; \
            cpasync16(dbase + (uint32_t)((m * ROWST + seg * 4) * 4), \
                      magb + (size_t)fmc * Tn + ttc, sz); \
        } \
        cp_commit(); }

    ISSUE(0, 0);
    ISSUE(1, 1);

    for (int k = 0; k < NTILE; ++k) {
        cp_wait1();
        __syncwarp();

        const float4* srow4 = reinterpret_cast<const float4*>(
            s_scan + (c * 2 + (k & 1)) * WBUF + l * ROWST);

        const bool live = (c > 0 || k >= WTILES);
        const bool outp = (k >= WTILES);

        if (live) {
            #pragma unroll
            for (int j8 = 0; j8 < 4; ++j8) {
                const int i = k * STILE + j8 * 8;
                if (i < LOCAL) {
                    float4 va = srow4[j8 * 2];
                    float4 vb = srow4[j8 * 2 + 1];
                    // off-critical-path products
                    float rx0 = rise * va.x, fx0 = fall * va.x;
                    float rx1 = rise * va.y, fx1 = fall * va.y;
                    float rx2 = rise * va.z, fx2 = fall * va.z;
                    float rx3 = rise * va.w, fx3 = fall * va.w;
                    float rx4 = rise * vb.x, fx4 = fall * vb.x;
                    float rx5 = rise * vb.y, fx5 = fall * vb.y;
                    float rx6 = rise * vb.z, fx6 = fall * vb.z;
                    float rx7 = rise * vb.w, fx7 = fall * vb.w;
                    float o0, o1, o2, o3, o4, o5, o6, o7;
                    nf = nf_step2(rx0, fx0, nf, cr1, cf1, fl_); o0 = __fdividef(va.x, fmaf(ns10, nf, 1e-7f));
                    nf = nf_step2(rx1, fx1, nf, cr1, cf1, fl_); o1 = __fdividef(va.y, fmaf(ns10, nf, 1e-7f));
                    nf = nf_step2(rx2, fx2, nf, cr1, cf1, fl_); o2 = __fdividef(va.z, fmaf(ns10, nf, 1e-7f));
                    nf = nf_step2(rx3, fx3, nf, cr1, cf1, fl_); o3 = __fdividef(va.w, fmaf(ns10, nf, 1e-7f));
                    nf = nf_step2(rx4, fx4, nf, cr1, cf1, fl_); o4 = __fdividef(vb.x, fmaf(ns10, nf, 1e-7f));
                    nf = nf_step2(rx5, fx5, nf, cr1, cf1, fl_); o5 = __fdividef(vb.y, fmaf(ns10, nf, 1e-7f));
                    nf = nf_step2(rx6, fx6, nf, cr1, cf1, fl_); o6 = __fdividef(vb.z, fmaf(ns10, nf, 1e-7f));
                    nf = nf_step2(rx7, fx7, nf, cr1, cf1, fl_); o7 = __fdividef(vb.w, fmaf(ns10, nf, 1e-7f));
                    if (outp && fvalid) {
                        H8 pk;
                        pk.a = __floats2half2_rn(o0, o1);
                        pk.b = __floats2half2_rn(o2, o3);
                        pk.c = __floats2half2_rn(o4, o5);
                        pk.d = __floats2half2_rn(o6, o7);
                        const int tg = c * CHUNK + (i - WARM);
                        *reinterpret_cast<H8*>(myout + tg) = pk;
                    }
                }
            }
        }
        __syncwarp();

        if (k + 2 < NTILE) ISSUE(k + 2, k & 1);
    }
    cp_wait0();
    #undef ISSUE
}

// ============================================================
// K2: HMMA band GEMM (frozen, 29.8us)
// ============================================================
extern __shared__ char k2_smem[];

__global__ __launch_bounds__(256, 2) void band_kernel(float* __restrict__ out)
{
    const int b   = blockIdx.y;
    const int t0  = blockIdx.x * TTILE;
    const int tid = threadIdx.x;
    const int wid = tid >> 5;
    const int lane = tid & 31;

    __half* As = reinterpret_cast<__half*>(k2_smem);             // [FPAD][AST]
    __half* Bs = reinterpret_cast<__half*>(k2_smem + A_BYTES);   // [NBn][BST]
    const uint32_t As_u = smem_u32(As);
    const uint32_t Bs_u = smem_u32(Bs);

    const size_t vbase = (size_t)b * Fn * Tn;
    #pragma unroll
    for (int it = 0; it < 9; ++it) {                 // A rows f < 144
        int i = tid + it * 256;
        int f = i >> 4;
        int c = i & 15;
        int t = t0 + c * 8;
        int sz = (f < Fn && t + 8 <= Tn) ? 16 : 0;
        int tc = (t + 8 <= Tn) ? t : 0;
        cpasync16(As_u + (uint32_t)((f * AST + c * 8) * 2),
                  g_vnr + vbase + (size_t)f * Tn + tc, sz);
    }
    #pragma unroll
    for (int it = 0; it < 9; ++it) {
        int i = tid + it * 256;
        if (i < NBn * BST / 8)
            cpasync16(Bs_u + (uint32_t)(i * 16), g_fbh + i * 8, 16);
    }
    cp_commit();
    #pragma unroll
    for (int it = 0; it < 8; ++it) {                 // A rows f in [144, 272)
        int i = tid + it * 256 + 144 * 16;
        int f = i >> 4;
        int c = i & 15;
        int t = t0 + c * 8;
        int sz = (f < Fn && t + 8 <= Tn) ? 16 : 0;
        int fc = (f < Fn) ? f : 0;
        int tc = (t + 8 <= Tn) ? t : 0;
        cpasync16(As_u + (uint32_t)((f * AST + c * 8) * 2),
                  g_vnr + vbase + (size_t)fc * Tn + tc, sz);
    }
    cp_commit();

    const int m0 = wid * 16;
    const int krow = (lane & 7) + ((lane >> 4) << 3);
    const int msel = ((lane >> 3) & 1) * 8;
    const uint32_t a_addr0 = As_u + (uint32_t)((krow * AST + m0 + msel) * 2);

    const int nrow = (lane & 7) + ((lane >> 4) << 3);
    const int ksel = ((lane >> 3) & 1) * 8;
    uint32_t b_addr0[4];
    #pragma unroll
    for (int j2 = 0; j2 < 4; ++j2)
        b_addr0[j2] = Bs_u + (uint32_t)(((j2 * 16 + nrow) * BST + ksel) * 2);

    float d[8][4];
    #pragma unroll
    for (int j = 0; j < 8; ++j)
        #pragma unroll
        for (int q = 0; q < 4; ++q) d[j][q] = 0.0f;

    cp_wait1();
    __syncthreads();

    for (int ks = 0; ks < KSPLIT; ++ks) {
        uint32_t a[4];
        ldsm_x4_t(a, a_addr0 + (uint32_t)(ks * 16 * AST * 2));
        #pragma unroll
        for (int j2 = 0; j2 < 4; ++j2) {
            uint32_t bbv[4];
            ldsm_x4(bbv, b_addr0[j2] + (uint32_t)(ks * 32));
            mma16816(d[j2 * 2],     a, bbv[0], bbv[1]);
            mma16816(d[j2 * 2 + 1], a, bbv[2], bbv[3]);
        }
    }

    cp_wait0();
    __syncthreads();

    for (int ks = KSPLIT; ks < KSTEPS; ++ks) {
        uint32_t a[4];
        ldsm_x4_t(a, a_addr0 + (uint32_t)(ks * 16 * AST * 2));
        #pragma unroll
        for (int j2 = 0; j2 < 4; ++j2) {
            uint32_t bbv[4];
            ldsm_x4(bbv, b_addr0[j2] + (uint32_t)(ks * 32));
            mma16816(d[j2 * 2],     a, bbv[0], bbv[1]);
            mma16816(d[j2 * 2 + 1], a, bbv[2], bbv[3]);
        }
    }

    __syncthreads();
    float* stg = reinterpret_cast<float*>(k2_smem);              // [NBn][OST]
    const int g  = lane >> 2;
    const int tp = lane & 3;
    #pragma unroll
    for (int j = 0; j < 8; ++j) {
        int n = j * 8 + 2 * tp;
        int t = m0 + g;
        stg[n * OST + t]           = d[j][0];
        stg[(n + 1) * OST + t]     = d[j][1];
        stg[n * OST + t + 8]       = d[j][2];
        stg[(n + 1) * OST + t + 8] = d[j][3];
    }
    __syncthreads();

    const int tmax = Tn - t0;
    float* ob = out + (size_t)b * NBn * Tn + t0;
    #pragma unroll
    for (int it = 0; it < 8; ++it) {
        int idx = tid + it * 256;
        int n = idx >> 5;
        int c = (idx & 31) * 4;
        if (c < tmax) {
            float4 v = *reinterpret_cast<float4*>(stg + n * OST + c);
            v.x = tanh_fast(v.x); v.y = tanh_fast(v.y);
            v.z = tanh_fast(v.z); v.w = tanh_fast(v.w);
            *reinterpret_cast<float4*>(ob + (size_t)n * Tn + c) = v;
        }
    }
}

// ============================================================
extern "C" void kernel_launch(void* const* d_in, const int* in_sizes, int n_in,
                              void* d_out, int out_size)
{
    const float* mag = (const float*)d_in[0];
    const float* fb  = (const float*)d_in[1];
    const float* ns  = (const float*)d_in[2];
    const float* rr  = (const float*)d_in[3];
    const float* rf  = (const float*)d_in[4];
    float* out = (float*)d_out;

    cudaFuncSetAttribute(scan_kernel, cudaFuncAttributeMaxDynamicSharedMemorySize, SCAN_SMEM);
    cudaFuncSetAttribute(band_kernel, cudaFuncAttributeMaxDynamicSharedMemorySize, SMEM_TOTAL);

    scan_kernel<<<SCAN_GRID + 8, 256, SCAN_SMEM>>>(mag, fb, ns, rr, rf);

    dim3 grid((Tn + TTILE - 1) / TTILE, Bn);   // 63 x 16
    band_kernel<<<grid, 256, SMEM_TOTAL>>>(out);
}

// round 17
// speedup vs baseline: 1.6211x; 1.6211x over previous
#include <cuda_runtime.h>
#include <cuda_fp16.h>
#include <cstdint>

#define Bn 16
#define Fn 257
#define FPAD 272
#define Tn 8000
#define NBn 64
#define TTILE 128
#define KSTEPS 17

// ---- staged scan v3 config (r14, proven 82.7us total) ----
#define NCH 8
#define CHUNK 1000
#define WARM 128
#define LOCAL (WARM + CHUNK)          // 1128
#define STILE 64
#define NTILE 18                      // 18*64 = 1152 >= LOCAL
#define WTILES (WARM / STILE)         // 2 dead tiles for chunk 0
#define ROWST 68                      // floats (272 B): LDS.128 conflict-free
#define O2ST 33                       // odd word stride -> conflict-free staging
#define WBUF (32 * ROWST)             // 2176 floats
#define O2OFF (8 * 2 * WBUF)          // 34816 floats
#define SCAN_SMEM ((O2OFF + 8 * 32 * O2ST) * 4)   // 173056 B
#define SCAN_GRID (Bn * 9)            // 144

// ---- band GEMM config ----
#define AST 136
#define BST 280
#define OST 132
#define A_BYTES (FPAD * AST * 2)
#define B_BYTES (NBn * BST * 2)
#define SMEM_TOTAL (A_BYTES + B_BYTES)
#define KSPLIT 9

// 65.8 MB fp16 scratch: g_vnr[b][f][t] = vnr/10 (t-contiguous)
__device__ __align__(128) __half g_vnr[(size_t)Bn * Fn * Tn];
__device__ __align__(128) __half g_fbh[NBn * BST];

__device__ __forceinline__ uint32_t smem_u32(const void* p) {
    uint32_t a;
    asm("{ .reg .u64 t; cvta.to.shared.u64 t, %1; cvt.u32.u64 %0, t; }" : "=r"(a) : "l"(p));
    return a;
}
__device__ __forceinline__ void cpasync16(uint32_t dst, const void* src, int sz) {
    asm volatile("cp.async.ca.shared.global [%0], [%1], 16, %2;" :: "r"(dst), "l"(src), "r"(sz));
}
// L2-only (no L1 allocation) — for use-once streaming tile loads
__device__ __forceinline__ void cpasync16cg(uint32_t dst, const void* src, int sz) {
    asm volatile("cp.async.cg.shared.global [%0], [%1], 16, %2;" :: "r"(dst), "l"(src), "r"(sz));
}
__device__ __forceinline__ void cp_commit() { asm volatile("cp.async.commit_group;" ::: "memory"); }
__device__ __forceinline__ void cp_wait0()  { asm volatile("cp.async.wait_group 0;" ::: "memory"); }
__device__ __forceinline__ void cp_wait1()  { asm volatile("cp.async.wait_group 1;" ::: "memory"); }

__device__ __forceinline__ void ldsm_x4_t(uint32_t a[4], uint32_t addr) {
    asm volatile("ldmatrix.sync.aligned.m8n8.x4.trans.shared.b16 {%0,%1,%2,%3}, [%4];"
        : "=r"(a[0]), "=r"(a[1]), "=r"(a[2]), "=r"(a[3]) : "r"(addr));
}
__device__ __forceinline__ void ldsm_x4(uint32_t a[4], uint32_t addr) {
    asm volatile("ldmatrix.sync.aligned.m8n8.x4.shared.b16 {%0,%1,%2,%3}, [%4];"
        : "=r"(a[0]), "=r"(a[1]), "=r"(a[2]), "=r"(a[3]) : "r"(addr));
}
__device__ __forceinline__ void mma16816(float d[4], const uint32_t a[4], uint32_t b0, uint32_t b1) {
    asm volatile("mma.sync.aligned.m16n8k16.row.col.f32.f16.f16.f32 "
        "{%0,%1,%2,%3}, {%4,%5,%6,%7}, {%8,%9}, {%0,%1,%2,%3};"
        : "+f"(d[0]), "+f"(d[1]), "+f"(d[2]), "+f"(d[3])
        : "r"(a[0]), "r"(a[1]), "r"(a[2]), "r"(a[3]), "r"(b0), "r"(b1));
}
__device__ __forceinline__ float tanh_fast(float x) {
    float y; asm("tanh.approx.f32 %0, %1;" : "=f"(y) : "f"(x)); return y;
}

__device__ __forceinline__ float nf_step(float x, float nf, float rise, float fall, float fl) {
    float d  = x - nf;
    float cr = fmaf(rise, d, nf);
    float cf = fmaf(fall, d, nf);
    return fmaxf(fmaxf(cr, cf), fl);
}

// ============================================================
// K1: staged scan v3 -> g_vnr fp16 (vnr/10)
// Block = 32 chains (b, fg) x 8 chunk-warps. Coalesced cp.async.cg
// tile loads (depth-2, wait_group 1), conflict-free LDS.128 reads,
// conflict-free half2 output staging, coalesced flush. No block syncs.
// Blocks >= SCAN_GRID: fused fb conversion.
// ============================================================
extern __shared__ float s_scan[];

__global__ __launch_bounds__(256, 1) void scan_kernel(
    const float* __restrict__ mag,
    const float* __restrict__ fbw,
    const float* __restrict__ p_ns,
    const float* __restrict__ p_rr,
    const float* __restrict__ p_rf)
{
    if (blockIdx.x >= SCAN_GRID) {
        int base = (blockIdx.x - SCAN_GRID) * 256 + threadIdx.x;
        for (int i = base; i < NBn * BST; i += 256 * 8) {
            int n = i / BST;
            int f = i - n * BST;
            g_fbh[i] = (f < Fn) ? __float2half_rn(__ldg(fbw + n * Fn + f)) : __float2half_rn(0.0f);
        }
        return;
    }

    const int bb = blockIdx.x / 9;
    const int fg = blockIdx.x % 9;
    const int c  = threadIdx.x >> 5;   // chunk (warp)
    const int l  = threadIdx.x & 31;   // chain lane

    const uint32_t sbase = smem_u32(s_scan);

    const float rise = 1.0f / (1.0f + expf(-__ldg(p_rr)));
    const float fall = 1.0f / (1.0f + expf(-__ldg(p_rf)));
    const float ns10 = 10.0f * fabsf(__ldg(p_ns));

    const int fmine = fg * 32 + l;
    const bool fvalid = (fmine < Fn);
    const size_t myrow = ((size_t)bb * Fn + (fvalid ? fmine : 0)) * Tn;

    // init min over first 20 frames: 5 x LDG.128 (single line per lane)
    const float4* ir = reinterpret_cast<const float4*>(mag + myrow);
    float4 a0 = __ldg(ir), a1 = __ldg(ir + 1), a2 = __ldg(ir + 2),
           a3 = __ldg(ir + 3), a4 = __ldg(ir + 4);
    float mn = fminf(fminf(fminf(a0.x, a0.y), fminf(a0.z, a0.w)),
               fminf(fminf(fminf(a1.x, a1.y), fminf(a1.z, a1.w)),
               fminf(fminf(fminf(a2.x, a2.y), fminf(a2.z, a2.w)),
               fminf(fminf(fminf(a3.x, a3.y), fminf(a3.z, a3.w)),
                     fminf(fminf(a4.x, a4.y), fminf(a4.z, a4.w))))));
    mn = fmaxf(mn, 1e-5f);
    const float fl_ = 0.5f * mn;
    float nf = mn;

    const int t0base = c * CHUNK - WARM;
    const float* magb = mag + (size_t)bb * Fn * Tn;

    #define ISSUE(k, sel) { \
        const int t0g = t0base + (k) * STILE; \
        const uint32_t dbase = sbase + (uint32_t)((c * 2 + (sel)) * WBUF * 4); \
        _Pragma("unroll") \
        for (int it = 0; it < 16; ++it) { \
            int o = l + 32 * it; \
            int m = o >> 4; \
            int seg = o & 15; \
            int tt = t0g + seg * 4; \
            int fm = fg * 32 + m; \
            int sz = (tt >= 0 && tt + 4 <= Tn && fm < Fn) ? 16 : 0; \
            int ttc = (tt < 0) ? 0 : ((tt + 4 > Tn) ? (Tn - 4) : tt); \
            int fmc = (fm < Fn) ? fm : 0; \
            cpasync16cg(dbase + (uint32_t)((m * ROWST + seg * 4) * 4), \
                        magb + (size_t)fmc * Tn + ttc, sz); \
        } \
        cp_commit(); }

    ISSUE(0, 0);
    ISSUE(1, 1);

    for (int k = 0; k < NTILE; ++k) {
        cp_wait1();
        __syncwarp();

        const float4* srow4 = reinterpret_cast<const float4*>(
            s_scan + (c * 2 + (k & 1)) * WBUF + l * ROWST);
        float* orow = s_scan + O2OFF + (c * 32 + l) * O2ST;

        const bool live = (c > 0 || k >= WTILES);
        const bool outp = (k >= WTILES);

        if (live) {
            #pragma unroll
            for (int j4 = 0; j4 < 16; ++j4) {
                const int i = k * STILE + j4 * 4;
                if (i < LOCAL) {
                    float4 v = srow4[j4];        // conflict-free LDS.128
                    float o0, o1, o2, o3;
                    nf = nf_step(v.x, nf, rise, fall, fl_); o0 = __fdividef(v.x, fmaf(ns10, nf, 1e-7f));
                    nf = nf_step(v.y, nf, rise, fall, fl_); o1 = __fdividef(v.y, fmaf(ns10, nf, 1e-7f));
                    nf = nf_step(v.z, nf, rise, fall, fl_); o2 = __fdividef(v.z, fmaf(ns10, nf, 1e-7f));
                    nf = nf_step(v.w, nf, rise, fall, fl_); o3 = __fdividef(v.w, fmaf(ns10, nf, 1e-7f));
                    if (outp) {
                        __half2 h0 = __floats2half2_rn(o0, o1);
                        __half2 h1 = __floats2half2_rn(o2, o3);
                        *reinterpret_cast<__half2*>(&orow[j4 * 2])     = h0;
                        *reinterpret_cast<__half2*>(&orow[j4 * 2 + 1]) = h1;
                    }
                }
            }
        }
        __syncwarp();

        if (outp) {
            const int tg = c * CHUNK + (k - WTILES) * STILE;
            const int nh = (((k + 1) * STILE < LOCAL ? (k + 1) * STILE : LOCAL) - k * STILE) >> 1;
            #pragma unroll
            for (int m = 0; m < 32; ++m) {
                const int fm = fg * 32 + m;
                if (fm < Fn && l < nh) {
                    float w = s_scan[O2OFF + (c * 32 + m) * O2ST + l];
                    *reinterpret_cast<__half2*>(
                        g_vnr + ((size_t)bb * Fn + fm) * Tn + tg + 2 * l) =
                        *reinterpret_cast<__half2*>(&w);
                }
            }
        }
        __syncwarp();

        if (k + 2 < NTILE) ISSUE(k + 2, k & 1);
    }
    cp_wait0();
    #undef ISSUE
}

// ============================================================
// K2: HMMA band GEMM (frozen, 29.8us)
// ============================================================
extern __shared__ char k2_smem[];

__global__ __launch_bounds__(256, 2) void band_kernel(float* __restrict__ out)
{
    const int b   = blockIdx.y;
    const int t0  = blockIdx.x * TTILE;
    const int tid = threadIdx.x;
    const int wid = tid >> 5;
    const int lane = tid & 31;

    __half* As = reinterpret_cast<__half*>(k2_smem);             // [FPAD][AST]
    __half* Bs = reinterpret_cast<__half*>(k2_smem + A_BYTES);   // [NBn][BST]
    const uint32_t As_u = smem_u32(As);
    const uint32_t Bs_u = smem_u32(Bs);

    const size_t vbase = (size_t)b * Fn * Tn;
    #pragma unroll
    for (int it = 0; it < 9; ++it) {                 // A rows f < 144
        int i = tid + it * 256;
        int f = i >> 4;
        int c = i & 15;
        int t = t0 + c * 8;
        int sz = (f < Fn && t + 8 <= Tn) ? 16 : 0;
        int tc = (t + 8 <= Tn) ? t : 0;
        cpasync16(As_u + (uint32_t)((f * AST + c * 8) * 2),
                  g_vnr + vbase + (size_t)f * Tn + tc, sz);
    }
    #pragma unroll
    for (int it = 0; it < 9; ++it) {
        int i = tid + it * 256;
        if (i < NBn * BST / 8)
            cpasync16(Bs_u + (uint32_t)(i * 16), g_fbh + i * 8, 16);
    }
    cp_commit();
    #pragma unroll
    for (int it = 0; it < 8; ++it) {                 // A rows f in [144, 272)
        int i = tid + it * 256 + 144 * 16;
        int f = i >> 4;
        int c = i & 15;
        int t = t0 + c * 8;
        int sz = (f < Fn && t + 8 <= Tn) ? 16 : 0;
        int fc = (f < Fn) ? f : 0;
        int tc = (t + 8 <= Tn) ? t : 0;
        cpasync16(As_u + (uint32_t)((f * AST + c * 8) * 2),
                  g_vnr + vbase + (size_t)fc * Tn + tc, sz);
    }
    cp_commit();

    const int m0 = wid * 16;
    const int krow = (lane & 7) + ((lane >> 4) << 3);
    const int msel = ((lane >> 3) & 1) * 8;
    const uint32_t a_addr0 = As_u + (uint32_t)((krow * AST + m0 + msel) * 2);

    const int nrow = (lane & 7) + ((lane >> 4) << 3);
    const int ksel = ((lane >> 3) & 1) * 8;
    uint32_t b_addr0[4];
    #pragma unroll
    for (int j2 = 0; j2 < 4; ++j2)
        b_addr0[j2] = Bs_u + (uint32_t)(((j2 * 16 + nrow) * BST + ksel) * 2);

    float d[8][4];
    #pragma unroll
    for (int j = 0; j < 8; ++j)
        #pragma unroll
        for (int q = 0; q < 4; ++q) d[j][q] = 0.0f;

    cp_wait1();
    __syncthreads();

    for (int ks = 0; ks < KSPLIT; ++ks) {
        uint32_t a[4];
        ldsm_x4_t(a, a_addr0 + (uint32_t)(ks * 16 * AST * 2));
        #pragma unroll
        for (int j2 = 0; j2 < 4; ++j2) {
            uint32_t bbv[4];
            ldsm_x4(bbv, b_addr0[j2] + (uint32_t)(ks * 32));
            mma16816(d[j2 * 2],     a, bbv[0], bbv[1]);
            mma16816(d[j2 * 2 + 1], a, bbv[2], bbv[3]);
        }
    }

    cp_wait0();
    __syncthreads();

    for (int ks = KSPLIT; ks < KSTEPS; ++ks) {
        uint32_t a[4];
        ldsm_x4_t(a, a_addr0 + (uint32_t)(ks * 16 * AST * 2));
        #pragma unroll
        for (int j2 = 0; j2 < 4; ++j2) {
            uint32_t bbv[4];
            ldsm_x4(bbv, b_addr0[j2] + (uint32_t)(ks * 32));
            mma16816(d[j2 * 2],     a, bbv[0], bbv[1]);
            mma16816(d[j2 * 2 + 1], a, bbv[2], bbv[3]);
        }
    }

    __syncthreads();
    float* stg = reinterpret_cast<float*>(k2_smem);              // [NBn][OST]
    const int g  = lane >> 2;
    const int tp = lane & 3;
    #pragma unroll
    for (int j = 0; j < 8; ++j) {
        int n = j * 8 + 2 * tp;
        int t = m0 + g;
        stg[n * OST + t]           = d[j][0];
        stg[(n + 1) * OST + t]     = d[j][1];
        stg[n * OST + t + 8]       = d[j][2];
        stg[(n + 1) * OST + t + 8] = d[j][3];
    }
    __syncthreads();

    const int tmax = Tn - t0;
    float* ob = out + (size_t)b * NBn * Tn + t0;
    #pragma unroll
    for (int it = 0; it < 8; ++it) {
        int idx = tid + it * 256;
        int n = idx >> 5;
        int c = (idx & 31) * 4;
        if (c < tmax) {
            float4 v = *reinterpret_cast<float4*>(stg + n * OST + c);
            v.x = tanh_fast(v.x); v.y = tanh_fast(v.y);
            v.z = tanh_fast(v.z); v.w = tanh_fast(v.w);
            *reinterpret_cast<float4*>(ob + (size_t)n * Tn + c) = v;
        }
    }
}

// ============================================================
extern "C" void kernel_launch(void* const* d_in, const int* in_sizes, int n_in,
                              void* d_out, int out_size)
{
    const float* mag = (const float*)d_in[0];
    const float* fb  = (const float*)d_in[1];
    const float* ns  = (const float*)d_in[2];
    const float* rr  = (const float*)d_in[3];
    const float* rf  = (const float*)d_in[4];
    float* out = (float*)d_out;

    cudaFuncSetAttribute(scan_kernel, cudaFuncAttributeMaxDynamicSharedMemorySize, SCAN_SMEM);
    cudaFuncSetAttribute(band_kernel, cudaFuncAttributeMaxDynamicSharedMemorySize, SMEM_TOTAL);

    scan_kernel<<<SCAN_GRID + 8, 256, SCAN_SMEM>>>(mag, fb, ns, rr, rf);

    dim3 grid((Tn + TTILE - 1) / TTILE, Bn);   // 63 x 16
    band_kernel<<<grid, 256, SMEM_TOTAL>>>(out);
}